// round 2
// baseline (speedup 1.0000x reference)
#include <cuda_runtime.h>
#include <math.h>

// Problem constants (fixed shapes)
#define N_    512
#define V_    6890
#define NJ_   24
#define NB_   10
#define NP_   207
#define KD_   218            // 207 pose + 10 betas*scale + 1 scale (for v_template)
#define Q_    (V_*3)         // 20670
#define NK_   95
#define NC_   (N_*3)         // 1536
#define NSPLIT 16

// ------------------------------- scratch -----------------------------------
__device__ float g_JT[NJ_*3];               // J_regressor @ v_template
__device__ float g_JS[NB_*NJ_*3];           // J_regressor @ shapedirs (per beta)
__device__ float g_coeff[N_*KD_];           // per-n GEMM coefficient vector
__device__ float g_A[N_*NJ_*12];            // per-n skinning transforms (3x4)
__device__ float g_verts[V_*NC_];           // verts, v-major: [v][n*3+c]
__device__ float g_part[NSPLIT*NK_*NC_];    // split-K partials for keypoint GEMM

// ---------------------------------------------------------------------------
// K1: JT[j,c] = sum_v Jreg[j,v]*vt[v,c];  JS[b,j,c] = sum_v Jreg[j,v]*sd[b,v*3+c]
// one block per output, 256-thread reduction
// ---------------------------------------------------------------------------
__global__ void k_jconst(const float* __restrict__ Jreg,
                         const float* __restrict__ vt,
                         const float* __restrict__ sd) {
    int o = blockIdx.x;              // 0..791  (72 JT + 720 JS)
    int tid = threadIdx.x;
    float s = 0.f;
    if (o < 72) {
        int j = o / 3, c = o % 3;
        const float* jr = Jreg + (size_t)j * V_;
        for (int v = tid; v < V_; v += 256)
            s += jr[v] * vt[v*3 + c];
    } else {
        int r = o - 72;
        int b = r / 72; int r2 = r % 72;
        int j = r2 / 3, c = r2 % 3;
        const float* jr = Jreg + (size_t)j * V_;
        const float* sp = sd + (size_t)b * Q_;
        for (int v = tid; v < V_; v += 256)
            s += jr[v] * sp[v*3 + c];
    }
    // block reduce
    __shared__ float red[8];
    for (int off = 16; off > 0; off >>= 1)
        s += __shfl_down_sync(0xffffffffu, s, off);
    if ((tid & 31) == 0) red[tid >> 5] = s;
    __syncthreads();
    if (tid == 0) {
        float t = 0.f;
        #pragma unroll
        for (int w = 0; w < 8; w++) t += red[w];
        if (o < 72) g_JT[o] = t;
        else        g_JS[o - 72] = t;
    }
}

// ---------------------------------------------------------------------------
// K2: per-n scale, coeff vector, J, and sequential FK -> A[n][24][12]
// one thread per n
// ---------------------------------------------------------------------------
__global__ void k_pern(const float* __restrict__ pose,
                       const float* __restrict__ betas,
                       const float* __restrict__ vt,
                       const float* __restrict__ sd,
                       const int*   __restrict__ parents) {
    int n = blockIdx.x * blockDim.x + threadIdx.x;
    if (n >= N_) return;
    const float* be = betas + n * NB_;

    // ---- scale via body height (4 vertices, y coord of v_ss) ----
    const int   iv[4]  = {2802, 6262, 2237, 6728};
    const float sg[4]  = {1.f, 1.f, -1.f, -1.f};
    float bh = 0.f;
    #pragma unroll
    for (int t = 0; t < 4; t++) {
        int q = iv[t]*3 + 1;
        float vy = vt[q];
        #pragma unroll
        for (int b = 0; b < NB_; b++) vy += be[b] * sd[(size_t)b*Q_ + q];
        bh += sg[t] * vy;
    }
    float scale = 1.66f / bh;

    // ---- coeff vector [218] ----
    float* cf = g_coeff + (size_t)n * KD_;
    const float* pn = pose + (size_t)n * NJ_ * 9;
    for (int j = 1; j < NJ_; j++) {
        #pragma unroll
        for (int e = 0; e < 9; e++) {
            float d = (e == 0 || e == 4 || e == 8) ? 1.f : 0.f;
            cf[(j-1)*9 + e] = pn[j*9 + e] - d;
        }
    }
    #pragma unroll
    for (int b = 0; b < NB_; b++) cf[207 + b] = scale * be[b];
    cf[217] = scale;

    // ---- joints J[n] = scale * (JT + betas @ JS) ----
    float Jl[NJ_][3];
    for (int j = 0; j < NJ_; j++) {
        #pragma unroll
        for (int c = 0; c < 3; c++) {
            float s = g_JT[j*3 + c];
            #pragma unroll
            for (int b = 0; b < NB_; b++) s += be[b] * g_JS[b*72 + j*3 + c];
            Jl[j][c] = scale * s;
        }
    }

    // ---- FK chain ----
    float Rg[NJ_][9], tg[NJ_][3];
    for (int i = 0; i < NJ_; i++) {
        float Ri[9];
        #pragma unroll
        for (int e = 0; e < 9; e++) Ri[e] = pn[i*9 + e];
        if (i == 0) {
            #pragma unroll
            for (int e = 0; e < 9; e++) Rg[0][e] = Ri[e];
            #pragma unroll
            for (int c = 0; c < 3; c++) tg[0][c] = Jl[0][c];
        } else {
            int p = parents[i];
            float jh[3] = {Jl[i][0]-Jl[p][0], Jl[i][1]-Jl[p][1], Jl[i][2]-Jl[p][2]};
            #pragma unroll
            for (int r = 0; r < 3; r++) {
                float p0 = Rg[p][r*3+0], p1 = Rg[p][r*3+1], p2 = Rg[p][r*3+2];
                #pragma unroll
                for (int c = 0; c < 3; c++)
                    Rg[i][r*3+c] = p0*Ri[c] + p1*Ri[3+c] + p2*Ri[6+c];
                tg[i][r] = tg[p][r] + p0*jh[0] + p1*jh[1] + p2*jh[2];
            }
        }
        // A = [Rg | tg - Rg @ J_orig]
        float* Ao = g_A + (size_t)n*288 + i*12;
        #pragma unroll
        for (int r = 0; r < 3; r++) {
            Ao[r*4+0] = Rg[i][r*3+0];
            Ao[r*4+1] = Rg[i][r*3+1];
            Ao[r*4+2] = Rg[i][r*3+2];
            Ao[r*4+3] = tg[i][r] - (Rg[i][r*3+0]*Jl[i][0] +
                                    Rg[i][r*3+1]*Jl[i][1] +
                                    Rg[i][r*3+2]*Jl[i][2]);
        }
    }
}

// ---------------------------------------------------------------------------
// K3: fused v_posed GEMM + LBS.  Tile: 32 n x 32 verts (96 q).  K = 218.
// Writes verts (+trans) in v-major layout g_verts[v][n*3+c].
// ---------------------------------------------------------------------------
#define MT 32
#define QT 96
#define SMEM1_FLOATS (MT*KD_ + 32*QT + MT*99 + MT*289 + MT*24)

__global__ void k_pass1(const float* __restrict__ posedirs,
                        const float* __restrict__ shapedirs,
                        const float* __restrict__ vtempl,
                        const float* __restrict__ lw,
                        const float* __restrict__ trans) {
    extern __shared__ float smem[];
    float* cf  = smem;                  // [32][218]
    float* Bs  = cf  + MT*KD_;          // [32][96]   chunk of B
    float* vps = Bs  + 32*QT;           // [32][99]   v_posed tile (padded)
    float* As  = vps + MT*99;           // [32][289]  A matrices (padded)
    float* ws  = As  + MT*289;          // [32][24]   lbs weights

    int tid = threadIdx.x;
    int v0 = blockIdx.x * 32;
    int n0 = blockIdx.y * MT;
    int q0 = v0 * 3;

    // ---- stage coeff, A, lbs weights ----
    for (int idx = tid; idx < MT*KD_; idx += 256) {
        int ni = idx / KD_, k = idx % KD_;
        cf[ni*KD_ + k] = g_coeff[(size_t)(n0+ni)*KD_ + k];
    }
    for (int idx = tid; idx < MT*288; idx += 256) {
        int ni = idx / 288, e = idx % 288;
        As[ni*289 + e] = g_A[(size_t)(n0+ni)*288 + e];
    }
    for (int idx = tid; idx < MT*24; idx += 256) {
        int vi = idx / 24, j = idx % 24;
        int v = v0 + vi;
        ws[vi*24 + j] = (v < V_) ? lw[(size_t)v*NJ_ + j] : 0.f;
    }
    __syncthreads();

    // ---- GEMM: vp[32n][96q] ----
    int tx = tid & 31, ty = tid >> 5;       // tx: q-group(3), ty: n-group(4)
    float acc[4][3] = {};
    for (int kc = 0; kc < KD_; kc += 32) {
        int kcn = min(32, KD_ - kc);
        for (int idx = tid; idx < kcn*QT; idx += 256) {
            int kk = idx / QT, qq = idx % QT;
            int k = kc + kk, q = q0 + qq;
            float val = 0.f;
            if (q < Q_) {
                if (k < 207)      val = posedirs[(size_t)k*Q_ + q];
                else if (k < 217) val = shapedirs[(size_t)(k-207)*Q_ + q];
                else              val = vtempl[q];
            }
            Bs[kk*QT + qq] = val;
        }
        __syncthreads();
        #pragma unroll 8
        for (int kk = 0; kk < kcn; kk++) {
            float b0 = Bs[kk*QT + tx*3 + 0];
            float b1 = Bs[kk*QT + tx*3 + 1];
            float b2 = Bs[kk*QT + tx*3 + 2];
            #pragma unroll
            for (int i = 0; i < 4; i++) {
                float a = cf[(ty*4 + i)*KD_ + kc + kk];
                acc[i][0] = fmaf(a, b0, acc[i][0]);
                acc[i][1] = fmaf(a, b1, acc[i][1]);
                acc[i][2] = fmaf(a, b2, acc[i][2]);
            }
        }
        __syncthreads();
    }
    #pragma unroll
    for (int i = 0; i < 4; i++)
        #pragma unroll
        for (int j = 0; j < 3; j++)
            vps[(ty*4 + i)*99 + tx*3 + j] = acc[i][j];
    __syncthreads();

    // ---- LBS epilogue: warp w -> 4 verts, lane -> n ----
    int lane = tid & 31, wid = tid >> 5;
    float vpx[4], vpy[4], vpz[4];
    #pragma unroll
    for (int vi = 0; vi < 4; vi++) {
        int vloc = wid*4 + vi;
        vpx[vi] = vps[lane*99 + vloc*3 + 0];
        vpy[vi] = vps[lane*99 + vloc*3 + 1];
        vpz[vi] = vps[lane*99 + vloc*3 + 2];
    }
    float vr[4][3] = {};
    #pragma unroll 4
    for (int j = 0; j < NJ_; j++) {
        float a[12];
        #pragma unroll
        for (int e = 0; e < 12; e++) a[e] = As[lane*289 + j*12 + e];
        #pragma unroll
        for (int vi = 0; vi < 4; vi++) {
            float wt = ws[(wid*4 + vi)*24 + j];
            #pragma unroll
            for (int r = 0; r < 3; r++) {
                float t = fmaf(a[r*4+0], vpx[vi],
                          fmaf(a[r*4+1], vpy[vi],
                          fmaf(a[r*4+2], vpz[vi], a[r*4+3])));
                vr[vi][r] = fmaf(wt, t, vr[vi][r]);
            }
        }
    }
    int n = n0 + lane;
    float t0 = trans[n*3+0], t1 = trans[n*3+1], t2 = trans[n*3+2];
    #pragma unroll
    for (int vi = 0; vi < 4; vi++) {
        int v = v0 + wid*4 + vi;
        if (v < V_) {
            g_verts[(size_t)v*NC_ + n*3 + 0] = vr[vi][0] + t0;
            g_verts[(size_t)v*NC_ + n*3 + 1] = vr[vi][1] + t1;
            g_verts[(size_t)v*NC_ + n*3 + 2] = vr[vi][2] + t2;
        }
    }
}

// ---------------------------------------------------------------------------
// K4: keypoint GEMM  [95 x V] @ [V x 1536], split-K x16, writes partials
// ---------------------------------------------------------------------------
#define KCHUNK 431   // ceil(6890/16)

__global__ void k_pass2(const float* __restrict__ body25,
                        const float* __restrict__ face) {
    __shared__ float rT[16][97];    // [vv][m]
    __shared__ float vs[16][128];   // [vv][col]
    int tid = threadIdx.x;
    int col0 = blockIdx.x * 128;
    int sp = blockIdx.y;
    int vbeg = sp * KCHUNK;
    int vend = min(V_, vbeg + KCHUNK);

    int tx = tid % 16, ty = tid / 16;     // tx: 8 cols, ty: 6 rows
    float acc[6][8] = {};

    for (int kb = vbeg; kb < vend; kb += 16) {
        int kn = min(16, vend - kb);
        for (int idx = tid; idx < 16*96; idx += 256) {
            int vv = idx % 16, m = idx / 16;
            float val = 0.f;
            if (vv < kn && m < NK_) {
                int v = kb + vv;
                val = (m < 25) ? body25[(size_t)m*V_ + v]
                               : face[(size_t)(m-25)*V_ + v];
            }
            rT[vv][m] = val;
        }
        for (int idx = tid; idx < 16*128; idx += 256) {
            int vv = idx / 128, cc = idx % 128;
            vs[vv][cc] = (vv < kn) ? g_verts[(size_t)(kb+vv)*NC_ + col0 + cc] : 0.f;
        }
        __syncthreads();
        #pragma unroll
        for (int kk = 0; kk < 16; kk++) {
            float a[6];
            #pragma unroll
            for (int i = 0; i < 6; i++) a[i] = rT[kk][ty*6 + i];
            float4 b0 = *reinterpret_cast<const float4*>(&vs[kk][tx*8]);
            float4 b1 = *reinterpret_cast<const float4*>(&vs[kk][tx*8 + 4]);
            #pragma unroll
            for (int i = 0; i < 6; i++) {
                acc[i][0] = fmaf(a[i], b0.x, acc[i][0]);
                acc[i][1] = fmaf(a[i], b0.y, acc[i][1]);
                acc[i][2] = fmaf(a[i], b0.z, acc[i][2]);
                acc[i][3] = fmaf(a[i], b0.w, acc[i][3]);
                acc[i][4] = fmaf(a[i], b1.x, acc[i][4]);
                acc[i][5] = fmaf(a[i], b1.y, acc[i][5]);
                acc[i][6] = fmaf(a[i], b1.z, acc[i][6]);
                acc[i][7] = fmaf(a[i], b1.w, acc[i][7]);
            }
        }
        __syncthreads();
    }
    float* pp = g_part + (size_t)sp * (NK_*NC_);
    #pragma unroll
    for (int i = 0; i < 6; i++) {
        int m = ty*6 + i;
        if (m < NK_) {
            #pragma unroll
            for (int j = 0; j < 8; j++)
                pp[(size_t)m*NC_ + col0 + tx*8 + j] = acc[i][j];
        }
    }
}

// ---------------------------------------------------------------------------
// K5: reduce split-K partials -> out[n][m][c]
// ---------------------------------------------------------------------------
__global__ void k_reduce(float* __restrict__ out) {
    int o = blockIdx.x * 256 + threadIdx.x;
    if (o >= NK_*NC_) return;
    float s = 0.f;
    #pragma unroll
    for (int sp = 0; sp < NSPLIT; sp++) s += g_part[(size_t)sp*(NK_*NC_) + o];
    int m = o / NC_, col = o % NC_;
    int n = col / 3, c = col % 3;
    out[(size_t)n*(NK_*3) + m*3 + c] = s;
}

// ---------------------------------------------------------------------------
extern "C" void kernel_launch(void* const* d_in, const int* in_sizes, int n_in,
                              void* d_out, int out_size) {
    const float* pose      = (const float*)d_in[0];
    const float* betas     = (const float*)d_in[1];
    const float* trans     = (const float*)d_in[2];
    const float* vtempl    = (const float*)d_in[3];
    const float* shapedirs = (const float*)d_in[4];
    const float* Jreg      = (const float*)d_in[5];
    const float* posedirs  = (const float*)d_in[6];
    const float* lw        = (const float*)d_in[7];
    const float* body25    = (const float*)d_in[8];
    const float* face      = (const float*)d_in[9];
    const int*   parents   = (const int*)d_in[10];

    (void)in_sizes; (void)n_in; (void)out_size;

    static const size_t SMEM1 = (size_t)SMEM1_FLOATS * sizeof(float);
    cudaFuncSetAttribute(k_pass1, cudaFuncAttributeMaxDynamicSharedMemorySize, (int)SMEM1);

    k_jconst<<<72 + NB_*72, 256>>>(Jreg, vtempl, shapedirs);
    k_pern<<<N_/256, 256>>>(pose, betas, vtempl, shapedirs, parents);
    k_pass1<<<dim3((V_ + 31)/32, N_/MT), 256, SMEM1>>>(posedirs, shapedirs, vtempl, lw, trans);
    k_pass2<<<dim3(NC_/128, NSPLIT), 256>>>(body25, face);
    k_reduce<<<(NK_*NC_ + 255)/256, 256>>>((float*)d_out);
}

// round 3
// speedup vs baseline: 1.2768x; 1.2768x over previous
#include <cuda_runtime.h>
#include <math.h>

// Problem constants
#define N_    512
#define V_    6890
#define NJ_   24
#define NB_   10
#define KD_   218            // 207 pose + 10 scale*betas + 1 scale
#define Q_    (V_*3)         // 20670
#define NK_   95
#define NC_   (N_*3)         // 1536

// pass1 tiling: block 64n x 384q (128 verts), 256 threads, thread 16n x 6q
#define P1_QB  54            // ceil(20670/384)
// pass2 split-K
#define NSPLIT2 24
#define KCH2    288          // ceil(6890/24)

// ------------------------------- scratch -----------------------------------
__device__ float g_JT[NJ_*3];
__device__ float g_JS[NB_*NJ_*3];
__device__ float g_coeffT[KD_*N_];          // [k][n]
__device__ float g_AT[NJ_*12*N_];           // [j*12+e][n]
__device__ float g_verts[V_*NC_];           // [v][n*3+c]
__device__ float g_RT[V_*96];               // transposed regressors [v][m] (m=95 padded to 96)
__device__ float g_part[NSPLIT2*NK_*NC_];

// ------------------------- packed f32x2 helpers -----------------------------
typedef unsigned long long u64;
__device__ __forceinline__ u64 fma2(u64 a, u64 b, u64 c) {
    u64 d; asm("fma.rn.f32x2 %0, %1, %2, %3;" : "=l"(d) : "l"(a), "l"(b), "l"(c)); return d;
}
__device__ __forceinline__ u64 dup2(float x) {
    u64 r; asm("mov.b64 %0, {%1, %1};" : "=l"(r) : "f"(x)); return r;
}
__device__ __forceinline__ float2 unpk2(u64 v) {
    float2 r; asm("mov.b64 {%0, %1}, %2;" : "=f"(r.x), "=f"(r.y) : "l"(v)); return r;
}

// ---------------------------------------------------------------------------
// K1: joint-regressor constants
// ---------------------------------------------------------------------------
__global__ void k_jconst(const float* __restrict__ Jreg,
                         const float* __restrict__ vt,
                         const float* __restrict__ sd) {
    int o = blockIdx.x;              // 0..791  (72 JT + 720 JS)
    int tid = threadIdx.x;
    float s = 0.f;
    if (o < 72) {
        int j = o / 3, c = o % 3;
        const float* jr = Jreg + (size_t)j * V_;
        for (int v = tid; v < V_; v += 256) s += jr[v] * vt[v*3 + c];
    } else {
        int r = o - 72;
        int b = r / 72; int r2 = r % 72;
        int j = r2 / 3, c = r2 % 3;
        const float* jr = Jreg + (size_t)j * V_;
        const float* sp = sd + (size_t)b * Q_;
        for (int v = tid; v < V_; v += 256) s += jr[v] * sp[v*3 + c];
    }
    __shared__ float red[8];
    for (int off = 16; off > 0; off >>= 1) s += __shfl_down_sync(0xffffffffu, s, off);
    if ((tid & 31) == 0) red[tid >> 5] = s;
    __syncthreads();
    if (tid == 0) {
        float t = 0.f;
        #pragma unroll
        for (int w = 0; w < 8; w++) t += red[w];
        if (o < 72) g_JT[o] = t;
        else        g_JS[o - 72] = t;
    }
}

// ---------------------------------------------------------------------------
// K2: per-n scale, coeff (transposed), FK -> A (transposed [e][n])
// ---------------------------------------------------------------------------
__global__ void k_pern(const float* __restrict__ pose,
                       const float* __restrict__ betas,
                       const float* __restrict__ vt,
                       const float* __restrict__ sd,
                       const int*   __restrict__ parents) {
    int n = blockIdx.x * blockDim.x + threadIdx.x;
    if (n >= N_) return;
    const float* be = betas + n * NB_;

    const int   iv[4]  = {2802, 6262, 2237, 6728};
    const float sg[4]  = {1.f, 1.f, -1.f, -1.f};
    float bh = 0.f;
    #pragma unroll
    for (int t = 0; t < 4; t++) {
        int q = iv[t]*3 + 1;
        float vy = vt[q];
        #pragma unroll
        for (int b = 0; b < NB_; b++) vy += be[b] * sd[(size_t)b*Q_ + q];
        bh += sg[t] * vy;
    }
    float scale = 1.66f / bh;

    const float* pn = pose + (size_t)n * NJ_ * 9;
    for (int j = 1; j < NJ_; j++) {
        #pragma unroll
        for (int e = 0; e < 9; e++) {
            float d = (e == 0 || e == 4 || e == 8) ? 1.f : 0.f;
            g_coeffT[((j-1)*9 + e)*N_ + n] = pn[j*9 + e] - d;
        }
    }
    #pragma unroll
    for (int b = 0; b < NB_; b++) g_coeffT[(207 + b)*N_ + n] = scale * be[b];
    g_coeffT[217*N_ + n] = scale;

    float Jl[NJ_][3];
    for (int j = 0; j < NJ_; j++) {
        #pragma unroll
        for (int c = 0; c < 3; c++) {
            float s = g_JT[j*3 + c];
            #pragma unroll
            for (int b = 0; b < NB_; b++) s += be[b] * g_JS[b*72 + j*3 + c];
            Jl[j][c] = scale * s;
        }
    }

    float Rg[NJ_][9], tg[NJ_][3];
    for (int i = 0; i < NJ_; i++) {
        float Ri[9];
        #pragma unroll
        for (int e = 0; e < 9; e++) Ri[e] = pn[i*9 + e];
        if (i == 0) {
            #pragma unroll
            for (int e = 0; e < 9; e++) Rg[0][e] = Ri[e];
            #pragma unroll
            for (int c = 0; c < 3; c++) tg[0][c] = Jl[0][c];
        } else {
            int p = parents[i];
            float jh[3] = {Jl[i][0]-Jl[p][0], Jl[i][1]-Jl[p][1], Jl[i][2]-Jl[p][2]};
            #pragma unroll
            for (int r = 0; r < 3; r++) {
                float p0 = Rg[p][r*3+0], p1 = Rg[p][r*3+1], p2 = Rg[p][r*3+2];
                #pragma unroll
                for (int c = 0; c < 3; c++)
                    Rg[i][r*3+c] = p0*Ri[c] + p1*Ri[3+c] + p2*Ri[6+c];
                tg[i][r] = tg[p][r] + p0*jh[0] + p1*jh[1] + p2*jh[2];
            }
        }
        #pragma unroll
        for (int r = 0; r < 3; r++) {
            g_AT[(i*12 + r*4 + 0)*N_ + n] = Rg[i][r*3+0];
            g_AT[(i*12 + r*4 + 1)*N_ + n] = Rg[i][r*3+1];
            g_AT[(i*12 + r*4 + 2)*N_ + n] = Rg[i][r*3+2];
            g_AT[(i*12 + r*4 + 3)*N_ + n] = tg[i][r] - (Rg[i][r*3+0]*Jl[i][0] +
                                                        Rg[i][r*3+1]*Jl[i][1] +
                                                        Rg[i][r*3+2]*Jl[i][2]);
        }
    }
}

// ---------------------------------------------------------------------------
// K3: transpose keypoint regressors -> g_RT[v][96] (row 95 zero)
// ---------------------------------------------------------------------------
__global__ void k_transpose(const float* __restrict__ b25,
                            const float* __restrict__ face) {
    int idx = blockIdx.x * 256 + threadIdx.x;
    if (idx >= V_*96) return;
    int v = idx / 96, m = idx - v*96;
    float val = 0.f;
    if (m < 25)      val = b25[(size_t)m*V_ + v];
    else if (m < 95) val = face[(size_t)(m-25)*V_ + v];
    g_RT[idx] = val;
}

// ---------------------------------------------------------------------------
// K4 (pass1): f32x2 GEMM [64n x 384q, K=218] + packed LBS epilogue
// smem union: GEMM {cfs[224][64], Bs[16][384]} | EPI {A_p[288][64], ws[128][25], trT[3][64]}
// ---------------------------------------------------------------------------
#define CFS_ROWS 224
#define SM1_FLOATS (288*64 + 128*25 + 3*64)   // 21824 (epi phase is larger)

__global__ void __launch_bounds__(256, 1)
k_pass1(const float* __restrict__ posedirs,
        const float* __restrict__ shapedirs,
        const float* __restrict__ vtempl,
        const float* __restrict__ lw,
        const float* __restrict__ trans) {
    extern __shared__ float sm[];
    float* cfs = sm;                     // [224][64]
    float* Bs  = sm + CFS_ROWS*64;       // [16][384]
    float* A_p = sm;                     // [288][64]
    float* ws  = sm + 288*64;            // [128][25]
    float* trT = sm + 288*64 + 128*25;   // [3][64]

    int tid = threadIdx.x;
    int q0 = blockIdx.x * 384;
    int v0 = blockIdx.x * 128;
    int n0 = blockIdx.y * 64;
    int row = tid >> 6, col = tid & 63;
    int nb  = row * 16;

    // stage full coeff chunk (transposed), zero-padded to 224 rows
    for (int idx = tid; idx < CFS_ROWS*64; idx += 256) {
        int k = idx >> 6, nn = idx & 63;
        cfs[idx] = (k < KD_) ? g_coeffT[k*N_ + n0 + nn] : 0.f;
    }

    u64 acc[8][6];
    #pragma unroll
    for (int i = 0; i < 8; i++)
        #pragma unroll
        for (int j = 0; j < 6; j++) acc[i][j] = 0ULL;

    for (int kc = 0; kc < CFS_ROWS; kc += 16) {
        __syncthreads();
        // stage B chunk [16][384]
        for (int idx = tid; idx < 16*384; idx += 256) {
            int kk = idx / 384, qq = idx - kk*384;
            int k = kc + kk, q = q0 + qq;
            float val = 0.f;
            if (q < Q_ && k < KD_) {
                if (k < 207)      val = posedirs[(size_t)k*Q_ + q];
                else if (k < 217) val = shapedirs[(size_t)(k-207)*Q_ + q];
                else              val = vtempl[q];
            }
            Bs[idx] = val;
        }
        __syncthreads();
        #pragma unroll 2
        for (int kk = 0; kk < 16; kk++) {
            const float* cr = &cfs[(kc+kk)*64 + nb];
            ulonglong2 A0 = *(const ulonglong2*)(cr);
            ulonglong2 A1 = *(const ulonglong2*)(cr + 4);
            ulonglong2 A2 = *(const ulonglong2*)(cr + 8);
            ulonglong2 A3 = *(const ulonglong2*)(cr + 12);
            u64 a2[8] = {A0.x, A0.y, A1.x, A1.y, A2.x, A2.y, A3.x, A3.y};
            const float* br = &Bs[kk*384 + col*6];
            #pragma unroll
            for (int qi = 0; qi < 6; qi++) {
                u64 b2 = dup2(br[qi]);
                #pragma unroll
                for (int np = 0; np < 8; np++)
                    acc[np][qi] = fma2(a2[np], b2, acc[np][qi]);
            }
        }
    }
    __syncthreads();

    // ---- stage epilogue data (reuses GEMM smem) ----
    for (int idx = tid; idx < 288*64; idx += 256)
        A_p[idx] = g_AT[(size_t)(idx >> 6)*N_ + n0 + (idx & 63)];
    for (int idx = tid; idx < 128*24; idx += 256) {
        int vloc = idx / 24, j = idx - vloc*24;
        int v = v0 + vloc;
        ws[vloc*25 + j] = (v < V_) ? lw[(size_t)v*NJ_ + j] : 0.f;
    }
    if (tid < 192) trT[(tid % 3)*64 + tid/3] = trans[(n0 + tid/3)*3 + (tid % 3)];
    __syncthreads();

    // ---- packed LBS: vr init = trans, accumulate over 24 joints ----
    #pragma unroll
    for (int vsel = 0; vsel < 2; vsel++) {
        int vloc = col*2 + vsel;
        u64 vr[8][3];
        #pragma unroll
        for (int np = 0; np < 8; np++)
            #pragma unroll
            for (int r = 0; r < 3; r++)
                vr[np][r] = *(const u64*)&trT[r*64 + nb + np*2];

        for (int j = 0; j < NJ_; j++) {
            u64 w2 = dup2(ws[vloc*25 + j]);
            const float* ab = &A_p[(j*12)*64 + nb];
            #pragma unroll
            for (int np = 0; np < 8; np++) {
                u64 x2 = acc[np][vsel*3 + 0];
                u64 y2 = acc[np][vsel*3 + 1];
                u64 z2 = acc[np][vsel*3 + 2];
                #pragma unroll
                for (int r = 0; r < 3; r++) {
                    const float* ae = ab + (r*4)*64 + np*2;
                    u64 t = *(const u64*)(ae + 3*64);
                    t = fma2(*(const u64*)(ae),         x2, t);
                    t = fma2(*(const u64*)(ae +  64),   y2, t);
                    t = fma2(*(const u64*)(ae + 128),   z2, t);
                    vr[np][r] = fma2(w2, t, vr[np][r]);
                }
            }
        }
        int v = v0 + vloc;
        if (v < V_) {
            float* dst = g_verts + (size_t)v*NC_ + (n0 + nb)*3;
            #pragma unroll
            for (int np = 0; np < 8; np += 2) {
                float2 p0 = unpk2(vr[np][0]),   p1 = unpk2(vr[np][1]),   p2 = unpk2(vr[np][2]);
                float2 r0 = unpk2(vr[np+1][0]), r1 = unpk2(vr[np+1][1]), r2 = unpk2(vr[np+1][2]);
                float4* d4 = (float4*)(dst + np*6);
                d4[0] = make_float4(p0.x, p1.x, p2.x, p0.y);
                d4[1] = make_float4(p1.y, p2.y, r0.x, r1.x);
                d4[2] = make_float4(r2.x, r0.y, r1.y, r2.y);
            }
        }
    }
}

// ---------------------------------------------------------------------------
// K5 (pass2): packed keypoint GEMM [96 x 1536], split-K x24
// block: 96m x 128c, thread 6m x 4 col-pairs (interleaved, conflict-free LDS.64)
// ---------------------------------------------------------------------------
__global__ void __launch_bounds__(256, 2)
k_pass2() {
    __shared__ float rT[16*96];
    __shared__ float vs[16*128];
    int tid = threadIdx.x;
    int tx = tid & 15, ty = tid >> 4;
    int col0 = blockIdx.x * 128;
    int sp = blockIdx.y;
    int vbeg = sp * KCH2;
    int vend = min(V_, vbeg + KCH2);

    u64 acc[6][4];
    #pragma unroll
    for (int r = 0; r < 6; r++)
        #pragma unroll
        for (int i = 0; i < 4; i++) acc[r][i] = 0ULL;

    for (int kb = vbeg; kb < vend; kb += 16) {
        int kn = min(16, vend - kb);
        __syncthreads();
        for (int idx = tid; idx < 16*96; idx += 256) {
            int kk = idx / 96, mm = idx - kk*96;
            rT[idx] = (kk < kn) ? g_RT[(size_t)(kb+kk)*96 + mm] : 0.f;
        }
        for (int idx = tid; idx < 16*128; idx += 256) {
            int kk = idx >> 7, cc = idx & 127;
            vs[idx] = (kk < kn) ? g_verts[(size_t)(kb+kk)*NC_ + col0 + cc] : 0.f;
        }
        __syncthreads();
        #pragma unroll 4
        for (int kk = 0; kk < 16; kk++) {
            u64 b2[4];
            #pragma unroll
            for (int i = 0; i < 4; i++)
                b2[i] = *(const u64*)&vs[kk*128 + 2*(tx + i*16)];
            #pragma unroll
            for (int r = 0; r < 6; r++) {
                u64 a2 = dup2(rT[kk*96 + ty*6 + r]);
                #pragma unroll
                for (int i = 0; i < 4; i++)
                    acc[r][i] = fma2(a2, b2[i], acc[r][i]);
            }
        }
    }
    float* pp = g_part + (size_t)sp * (NK_*NC_);
    #pragma unroll
    for (int r = 0; r < 6; r++) {
        int m = ty*6 + r;
        if (m < NK_) {
            #pragma unroll
            for (int i = 0; i < 4; i++) {
                float2 p = unpk2(acc[r][i]);
                *(float2*)&pp[(size_t)m*NC_ + col0 + 2*(tx + i*16)] = p;
            }
        }
    }
}

// ---------------------------------------------------------------------------
// K6: reduce split-K partials -> out[n][m][c]
// ---------------------------------------------------------------------------
__global__ void k_reduce(float* __restrict__ out) {
    int o = blockIdx.x * 256 + threadIdx.x;
    if (o >= NK_*NC_) return;
    float s = 0.f;
    #pragma unroll
    for (int sp = 0; sp < NSPLIT2; sp++) s += g_part[(size_t)sp*(NK_*NC_) + o];
    int m = o / NC_, c2 = o % NC_;
    int n = c2 / 3, c = c2 % 3;
    out[(size_t)n*(NK_*3) + m*3 + c] = s;
}

// ---------------------------------------------------------------------------
extern "C" void kernel_launch(void* const* d_in, const int* in_sizes, int n_in,
                              void* d_out, int out_size) {
    const float* pose      = (const float*)d_in[0];
    const float* betas     = (const float*)d_in[1];
    const float* trans     = (const float*)d_in[2];
    const float* vtempl    = (const float*)d_in[3];
    const float* shapedirs = (const float*)d_in[4];
    const float* Jreg      = (const float*)d_in[5];
    const float* posedirs  = (const float*)d_in[6];
    const float* lw        = (const float*)d_in[7];
    const float* body25    = (const float*)d_in[8];
    const float* face      = (const float*)d_in[9];
    const int*   parents   = (const int*)d_in[10];

    (void)in_sizes; (void)n_in; (void)out_size;

    static const int SM1 = SM1_FLOATS * sizeof(float);   // 87296 B
    cudaFuncSetAttribute(k_pass1, cudaFuncAttributeMaxDynamicSharedMemorySize, SM1);

    k_jconst<<<72 + NB_*72, 256>>>(Jreg, vtempl, shapedirs);
    k_pern<<<N_/256, 256>>>(pose, betas, vtempl, shapedirs, parents);
    k_transpose<<<(V_*96 + 255)/256, 256>>>(body25, face);
    k_pass1<<<dim3(P1_QB, N_/64), 256, SM1>>>(posedirs, shapedirs, vtempl, lw, trans);
    k_pass2<<<dim3(NC_/128, NSPLIT2), 256>>>();
    k_reduce<<<(NK_*NC_ + 255)/256, 256>>>((float*)d_out);
}